// round 14
// baseline (speedup 1.0000x reference)
#include <cuda_runtime.h>
#include <cuda_fp16.h>
#include <math.h>

typedef unsigned int u32;

#define SLEN 2048
#define DMODEL 2048
#define NH 16
#define NKV 4
#define HD 128
#define MX (SLEN * DMODEL)          // 4194304
#define MKV (SLEN * NKV * HD)       // 1048576
#define WKV (NKV * HD * DMODEL)     // 1048576
#define N4X (MX / 4)                // 1048576 float4 items
#define N4KV (WKV / 4)              // 262144

// fp32 packed QKV projection output: [s][3072] (q 0-2047, k 2048-2559, v 2560-3071)
__device__ __align__(16) float g_qkvf[SLEN * 3072];

// fp16 operands
__device__ __align__(16) __half s_xh[MX];                    // x single
__device__ __align__(16) __half s_wqkvh[3072 * DMODEL];      // packed wq|wk|wv, single
__device__ __align__(16) __half s_woh[MX];                   // wo, single
__device__ __align__(16) __half s_qh[MX];                    // q single (post norm+rope, pre-scaled)
__device__ __align__(16) __half s_kh[MKV];                   // k single (post norm+rope)
__device__ __align__(16) __half s_vh[MKV];                   // v single
__device__ __align__(16) __half s_ath[MX];                   // attention out single

// ---------------------------------------------------------------------------
// helpers
// ---------------------------------------------------------------------------
__device__ __forceinline__ u32 sptr(const void* p) {
    return (u32)__cvta_generic_to_shared(p);
}
__device__ __forceinline__ void ldm4(u32 a, u32& r0, u32& r1, u32& r2, u32& r3) {
    asm volatile("ldmatrix.sync.aligned.m8n8.x4.shared.b16 {%0,%1,%2,%3},[%4];"
                 : "=r"(r0), "=r"(r1), "=r"(r2), "=r"(r3) : "r"(a));
}
__device__ __forceinline__ void ldm4t(u32 a, u32& r0, u32& r1, u32& r2, u32& r3) {
    asm volatile("ldmatrix.sync.aligned.m8n8.x4.trans.shared.b16 {%0,%1,%2,%3},[%4];"
                 : "=r"(r0), "=r"(r1), "=r"(r2), "=r"(r3) : "r"(a));
}
__device__ __forceinline__ void mma_h(float* c, u32 a0, u32 a1, u32 a2, u32 a3,
                                      u32 b0, u32 b1) {
    asm volatile(
        "mma.sync.aligned.m16n8k16.row.col.f32.f16.f16.f32 "
        "{%0,%1,%2,%3},{%4,%5,%6,%7},{%8,%9},{%0,%1,%2,%3};"
        : "+f"(c[0]), "+f"(c[1]), "+f"(c[2]), "+f"(c[3])
        : "r"(a0), "r"(a1), "r"(a2), "r"(a3), "r"(b0), "r"(b1));
}
__device__ __forceinline__ u32 pack2h(__half a, __half b) {
    __half2 t = __halves2half2(a, b);
    return *reinterpret_cast<u32*>(&t);
}
__device__ __forceinline__ u32 cvt2h(float x, float y) {
    return pack2h(__float2half_rn(x), __float2half_rn(y));
}
__device__ __forceinline__ float ex2(float x) {
    float y; asm("ex2.approx.f32 %0, %1;" : "=f"(y) : "f"(x)); return y;
}
__device__ __forceinline__ u32 ex2h2(u32 x) {
    u32 y; asm("ex2.approx.f16x2 %0, %1;" : "=r"(y) : "r"(x)); return y;
}
__device__ __forceinline__ void cpa16(u32 dst, const void* src) {
    asm volatile("cp.async.cg.shared.global [%0], [%1], 16;" :: "r"(dst), "l"(src));
}
__device__ __forceinline__ void cpcommit() {
    asm volatile("cp.async.commit_group;");
}
template <int N>
__device__ __forceinline__ void cpwait() {
    asm volatile("cp.async.wait_group %0;" :: "n"(N));
}

// ---------------------------------------------------------------------------
// merged prep: convert x -> xh ; wq|wk|wv -> wqkvh ; wo -> woh (all single)
// ---------------------------------------------------------------------------
__global__ __launch_bounds__(256) void prep_all(
    const float* __restrict__ x, const float* __restrict__ wq,
    const float* __restrict__ wk, const float* __restrict__ wv,
    const float* __restrict__ wo,
    __half* __restrict__ xh, __half* __restrict__ wqkvh, __half* __restrict__ woh)
{
    int i = blockIdx.x * blockDim.x + threadIdx.x;
    if (i < N4X) {
        float4 v = ((const float4*)x)[i];
        ((u32*)xh)[i * 2]     = cvt2h(v.x, v.y);
        ((u32*)xh)[i * 2 + 1] = cvt2h(v.z, v.w);
        return;
    }
    i -= N4X;
    if (i < N4X) {
        float4 v = ((const float4*)wq)[i];
        ((u32*)wqkvh)[i * 2]     = cvt2h(v.x, v.y);
        ((u32*)wqkvh)[i * 2 + 1] = cvt2h(v.z, v.w);
        return;
    }
    i -= N4X;
    if (i < N4KV) {
        float4 v = ((const float4*)wk)[i];
        u32* dst = (u32*)(wqkvh + MX);
        dst[i * 2]     = cvt2h(v.x, v.y);
        dst[i * 2 + 1] = cvt2h(v.z, v.w);
        return;
    }
    i -= N4KV;
    if (i < N4KV) {
        float4 v = ((const float4*)wv)[i];
        u32* dst = (u32*)(wqkvh + MX + WKV);
        dst[i * 2]     = cvt2h(v.x, v.y);
        dst[i * 2 + 1] = cvt2h(v.z, v.w);
        return;
    }
    i -= N4KV;
    {
        float4 v = ((const float4*)wo)[i];
        ((u32*)woh)[i * 2]     = cvt2h(v.x, v.y);
        ((u32*)woh)[i * 2 + 1] = cvt2h(v.z, v.w);
    }
}

// ---------------------------------------------------------------------------
// C[M,N] = A[M,K] @ B[N,K]^T ; both single fp16, 1-term MMA.
// 128x128x32 tiles, 256 thr (8 warps: 4m x 2n), 3-stage cp.async ring.
// ---------------------------------------------------------------------------
__global__ __launch_bounds__(256, 2) void gemm1(
    const __half* __restrict__ Ah, const __half* __restrict__ Bh,
    float* __restrict__ C, int M, int N, int K)
{
    extern __shared__ char smd[];
    const u32 smb = sptr(smd);
    const int tid = threadIdx.x, lane = tid & 31, w = tid >> 5;
    const int wm = w >> 1, wn = w & 1;
    const int bm = blockIdx.y * 128, bn = blockIdx.x * 128;

    float acc[2][8][4];
#pragma unroll
    for (int a = 0; a < 2; a++)
#pragma unroll
        for (int b = 0; b < 8; b++)
#pragma unroll
            for (int c = 0; c < 4; c++) acc[a][b][c] = 0.f;

    const u32 aoff = (wm * 32 + (lane & 15)) * 80 + (lane >> 4) * 16;
    const u32 boff = 10240 + (wn * 64 + (lane >> 4) * 8 + (lane & 7)) * 80
                     + ((lane >> 3) & 1) * 16;

    auto load_stage = [&](int stg, int k0) {
        u32 sb = smb + stg * 20480;
#pragma unroll
        for (int p = 0; p < 2; p++) {
            int c = tid + p * 256;
            int row = c >> 2, kc = (c & 3) * 8;
            u32 d = sb + row * 80 + kc * 2;
            size_t ga = (size_t)(bm + row) * K + k0 + kc;
            size_t gb = (size_t)(bn + row) * K + k0 + kc;
            cpa16(d,         Ah + ga);
            cpa16(d + 10240, Bh + gb);
        }
        cpcommit();
    };

    const int NCH = K >> 5;
    load_stage(0, 0);
    load_stage(1, 32);

    int stg = 0;
    for (int ic = 0; ic < NCH; ic++) {
        if (ic + 2 < NCH) {
            int nxt = stg + 2; if (nxt >= 3) nxt -= 3;
            load_stage(nxt, (ic + 2) * 32);
            cpwait<2>();
        } else if (ic + 1 < NCH) {
            cpwait<1>();
        } else {
            cpwait<0>();
        }
        __syncthreads();
        const u32 base = smb + stg * 20480;
        const u32 a_ = base + aoff;
        const u32 b_ = base + boff;
#pragma unroll
        for (int ks = 0; ks < 2; ks++) {
            u32 ah[2][4];
            ldm4(a_ + ks * 32,        ah[0][0], ah[0][1], ah[0][2], ah[0][3]);
            ldm4(a_ + ks * 32 + 1280, ah[1][0], ah[1][1], ah[1][2], ah[1][3]);
#pragma unroll
            for (int g = 0; g < 4; g++) {
                u32 bh[4];
                ldm4(b_ + g * 1280 + ks * 32, bh[0], bh[1], bh[2], bh[3]);
#pragma unroll
                for (int mt = 0; mt < 2; mt++)
#pragma unroll
                    for (int s = 0; s < 2; s++)
                        mma_h(acc[mt][g * 2 + s],
                              ah[mt][0], ah[mt][1], ah[mt][2], ah[mt][3],
                              bh[2 * s], bh[2 * s + 1]);
            }
        }
        __syncthreads();
        stg = (stg + 1 == 3) ? 0 : stg + 1;
    }

#pragma unroll
    for (int mt = 0; mt < 2; mt++)
#pragma unroll
        for (int nt = 0; nt < 8; nt++) {
            int row = bm + wm * 32 + mt * 16 + (lane >> 2);
            int col = bn + wn * 64 + nt * 8 + (lane & 3) * 2;
            *(float2*)&C[(size_t)row * N + col] =
                make_float2(acc[mt][nt][0], acc[mt][nt][1]);
            *(float2*)&C[(size_t)(row + 8) * N + col] =
                make_float2(acc[mt][nt][2], acc[mt][nt][3]);
        }
}

// ---------------------------------------------------------------------------
// RMSNorm + RoPE + convert from packed qkv fp32.
// q PRE-SCALED by scale*log2e; all outputs single fp16.
// ---------------------------------------------------------------------------
__global__ __launch_bounds__(256) void norm_rope_cvt(
    const float* __restrict__ qkvf, const float* __restrict__ freqs,
    __half* __restrict__ qh, __half* __restrict__ kh, __half* __restrict__ vh)
{
    const float CS = 0.08838834764831845f * 1.4426950408889634f; // scale*log2e
    int gwarp = (blockIdx.x * blockDim.x + threadIdx.x) >> 5;
    int lane  = threadIdx.x & 31;
    const int total = SLEN * 24;
    if (gwarp >= total) return;
    int s = gwarp / 24;
    int h = gwarp % 24;

    if (h >= 20) {
        const float* row = qkvf + (size_t)s * 3072 + 2560 + (h - 20) * 128;
        float4 x = *(const float4*)&row[lane * 4];
        size_t idx = ((((size_t)s * NKV + (h - 20)) * HD) >> 1) + lane * 2;
        ((u32*)vh)[idx]     = cvt2h(x.x, x.y);
        ((u32*)vh)[idx + 1] = cvt2h(x.z, x.w);
        return;
    }

    bool isq = (h < 16);
    const float* row = qkvf + (size_t)s * 3072 + (isq ? h * 128 : 2048 + (h - 16) * 128);
    float4 x = *(const float4*)&row[lane * 4];
    float ss = x.x * x.x + x.y * x.y + x.z * x.z + x.w * x.w;
#pragma unroll
    for (int off = 16; off; off >>= 1)
        ss += __shfl_xor_sync(0xffffffffu, ss, off);
    float r = rsqrtf(ss * (1.f / 128.f) + 1.1920929e-07f);
    if (isq) r *= CS;

    float4 fc = *(const float4*)&freqs[(size_t)s * 128 + lane * 4];
    float x1 = x.x * r, x2 = x.y * r, x3 = x.z * r, x4 = x.w * r;
    float o0 = x1 * fc.x - x2 * fc.y;
    float o1 = x1 * fc.y + x2 * fc.x;
    float o2 = x3 * fc.z - x4 * fc.w;
    float o3 = x3 * fc.w + x4 * fc.z;

    if (isq) {
        size_t idx = ((((size_t)s * NH + h) * HD) >> 1) + lane * 2;
        ((u32*)qh)[idx]     = cvt2h(o0, o1);
        ((u32*)qh)[idx + 1] = cvt2h(o2, o3);
    } else {
        size_t idx = ((((size_t)s * NKV + (h - 16)) * HD) >> 1) + lane * 2;
        ((u32*)kh)[idx]     = cvt2h(o0, o1);
        ((u32*)kh)[idx + 1] = cvt2h(o2, o3);
    }
}

// ---------------------------------------------------------------------------
// Flash attention (causal, sink), FA2 warp layout: 4 warps (128 thr), each
// warp owns 16 q-rows x full 64-wide KV tile. q/k/v/P single fp16.
// K PING-PONG buffers: K(kt+1) prefetches into the other buffer during QK
// and softmax -> only 2 __syncthreads per iter. P computed directly in fp16
// via ex2.approx.f16x2 (result register IS the PV A-fragment).
// Grid (NH, NQT) heavy-first.
// smem: Q 0 (17408), K0 17408, K1 34816, V 52224 -> 69632 B (3 CTA/SM).
// ---------------------------------------------------------------------------
__global__ __launch_bounds__(128, 3) void attn_kernel(
    const __half* __restrict__ qh, const __half* __restrict__ kh,
    const __half* __restrict__ vh, const float* __restrict__ sinks,
    __half* __restrict__ ath)
{
    extern __shared__ char smr[];
    const u32 smb = sptr(smr);

    const int tid = threadIdx.x, lane = tid & 31, w = tid >> 5;
    const int h = blockIdx.x, kvh = h >> 2;
    const int qt = gridDim.y - 1 - blockIdx.y;   // heavy tiles launch first

    // async-load Q tile (single): 64 rows x 256B
#pragma unroll
    for (int i = 0; i < 8; i++) {
        int c = tid + i * 128;
        int r = c >> 4, ck = c & 15;
        u32 d = smb + r * 272 + ck * 16;
        size_t g = ((size_t)(qt * 64 + r) * NH + h) * HD + ck * 8;
        cpa16(d, qh + g);
    }
    auto load_k = [&](int kt, int buf) {
        u32 kbase = smb + 17408 + buf * 17408;
#pragma unroll
        for (int i = 0; i < 4; i++) {
            int c = tid + i * 128;
            int r = c >> 3, ck = c & 7;
            u32 d = kbase + r * 272 + ck * 32;
            size_t g = ((size_t)(kt * 64 + r) * NKV + kvh) * HD + ck * 16;
            cpa16(d,      kh + g);
            cpa16(d + 16, kh + g + 8);
        }
        cpcommit();
    };
    auto load_v = [&](int kt) {
#pragma unroll
        for (int i = 0; i < 4; i++) {
            int c = tid + i * 128;
            int r = c >> 3, ck = c & 7;
            u32 d = smb + 52224 + r * 272 + ck * 32;
            size_t g = ((size_t)(kt * 64 + r) * NKV + kvh) * HD + ck * 16;
            cpa16(d,      vh + g);
            cpa16(d + 16, vh + g + 8);
        }
        cpcommit();
    };
    load_k(0, 0);   // Q + K(0) in one group

    float oacc[16][4];
#pragma unroll
    for (int a = 0; a < 16; a++)
#pragma unroll
        for (int c = 0; c < 4; c++) oacc[a][c] = 0.f;
    float mrow[2] = {-1e30f, -1e30f}, lrow[2] = {0.f, 0.f};

    const u32 qa = smb + (w * 16 + (lane & 15)) * 272 + (lane >> 4) * 16;
    const u32 kboff = ((lane >> 4) * 8 + (lane & 7)) * 272 + ((lane >> 3) & 1) * 16;
    const u32 vb = smb + 52224 + (((lane >> 3) & 1) * 8 + (lane & 7)) * 272
                   + ((lane >> 4) * 8) * 2;

    for (int kt = 0; kt <= qt; kt++) {
        cpwait<0>();       // K(kt) (+Q first iter; V(kt-1) earlier) arrived
        __syncthreads();   // (B) K visible to all warps; prev PV done with V

        load_v(kt);                            // V(kt) flies during QK+softmax
        if (kt < qt) load_k(kt + 1, (kt + 1) & 1);  // K(kt+1) -> other buffer

        // S = q K^T : m16 n64 k128 per warp, single-term
        const u32 kb = smb + 17408 + (kt & 1) * 17408 + kboff;
        float sacc[8][4];
#pragma unroll
        for (int a = 0; a < 8; a++)
#pragma unroll
            for (int c = 0; c < 4; c++) sacc[a][c] = 0.f;

#pragma unroll
        for (int ks = 0; ks < 8; ks++) {
            u32 ah0, ah1, ah2, ah3;
            ldm4(qa + ks * 32, ah0, ah1, ah2, ah3);
#pragma unroll
            for (int g = 0; g < 4; g++) {
                u32 bh[4];
                ldm4(kb + g * 4352 + ks * 32, bh[0], bh[1], bh[2], bh[3]);
#pragma unroll
                for (int s = 0; s < 2; s++)
                    mma_h(sacc[g * 2 + s], ah0, ah1, ah2, ah3,
                          bh[2 * s], bh[2 * s + 1]);
            }
        }
        // no sync needed: K(kt+1) targets the other buffer

        // causal mask on diagonal tile
        if (kt == qt) {
            int r0 = qt * 64 + w * 16 + (lane >> 2);
#pragma unroll
            for (int nt = 0; nt < 8; nt++) {
                int col0 = kt * 64 + nt * 8 + (lane & 3) * 2;
#pragma unroll
                for (int ci = 0; ci < 4; ci++) {
                    int row = r0 + ((ci >= 2) ? 8 : 0);
                    int col = col0 + (ci & 1);
                    if (col > row) sacc[nt][ci] = -1e30f;
                }
            }
        }

        // softmax: quad-local rows; p computed directly in fp16x2
        u32 preg[2][8];
        float alpha[2];
#pragma unroll
        for (int i = 0; i < 2; i++) {
            float rm = -1e30f;
#pragma unroll
            for (int nt = 0; nt < 8; nt++)
                rm = fmaxf(rm, fmaxf(sacc[nt][2 * i], sacc[nt][2 * i + 1]));
            rm = fmaxf(rm, __shfl_xor_sync(0xffffffffu, rm, 1));
            rm = fmaxf(rm, __shfl_xor_sync(0xffffffffu, rm, 2));
            float mn = fmaxf(mrow[i], rm);
            alpha[i] = ex2(mrow[i] - mn);
            mrow[i] = mn;
            float rs = 0.f;
#pragma unroll
            for (int nt = 0; nt < 8; nt++) {
                u32 xp = cvt2h(sacc[nt][2 * i] - mn, sacc[nt][2 * i + 1] - mn);
                u32 pp = ex2h2(xp);
                preg[i][nt] = pp;
                float2 pf = __half22float2(*reinterpret_cast<__half2*>(&pp));
                rs += pf.x + pf.y;
            }
            rs += __shfl_xor_sync(0xffffffffu, rs, 1);
            rs += __shfl_xor_sync(0xffffffffu, rs, 2);
            lrow[i] = lrow[i] * alpha[i] + rs;
#pragma unroll
            for (int nt = 0; nt < 16; nt++) {
                oacc[nt][2 * i]     *= alpha[i];
                oacc[nt][2 * i + 1] *= alpha[i];
            }
        }

        cpwait<1>();       // V(kt) done (K(kt+1) may still fly)
        if (kt == qt) cpwait<0>();
        __syncthreads();   // (D) V visible to all warps

        // O += P V : m16 n128 k64, P fragments straight from preg
#pragma unroll
        for (int j = 0; j < 4; j++) {
            u32 ph0 = preg[0][2 * j],     ph1 = preg[1][2 * j];
            u32 ph2 = preg[0][2 * j + 1], ph3 = preg[1][2 * j + 1];
#pragma unroll
            for (int g = 0; g < 8; g++) {
                u32 bh[4];
                ldm4t(vb + j * 4352 + g * 32, bh[0], bh[1], bh[2], bh[3]);
#pragma unroll
                for (int s = 0; s < 2; s++)
                    mma_h(oacc[g * 2 + s], ph0, ph1, ph2, ph3,
                          bh[2 * s], bh[2 * s + 1]);
            }
        }
    }

    // epilogue: lse, sink sigmoid, normalize, single-fp16 store
    float sk = sinks[h];
#pragma unroll
    for (int i = 0; i < 2; i++) {
        float lse = mrow[i] * 0.6931471805599453f + logf(lrow[i]);
        float sg = 1.f / (1.f + expf(sk - lse));
        float sc = sg / lrow[i];
        int row = qt * 64 + w * 16 + (lane >> 2) + i * 8;
        size_t rb = (size_t)row * DMODEL + h * HD;
#pragma unroll
        for (int nt = 0; nt < 16; nt++) {
            int col = nt * 8 + (lane & 3) * 2;
            ((u32*)ath)[(rb + col) >> 1] =
                cvt2h(oacc[nt][2 * i] * sc, oacc[nt][2 * i + 1] * sc);
        }
    }
}

// ---------------------------------------------------------------------------
extern "C" void kernel_launch(void* const* d_in, const int* in_sizes, int n_in,
                              void* d_out, int out_size)
{
    const float* x     = (const float*)d_in[0];
    const float* freqs = (const float*)d_in[1];
    const float* wq    = (const float*)d_in[2];
    const float* wk    = (const float*)d_in[3];
    const float* wv    = (const float*)d_in[4];
    const float* wo    = (const float*)d_in[5];
    const float* sinks = (const float*)d_in[6];
    float* out = (float*)d_out;

    float* qkvf;
    __half *xh, *wqkvh, *woh, *qh, *kh, *vh, *ath;
    cudaGetSymbolAddress((void**)&qkvf,  g_qkvf);
    cudaGetSymbolAddress((void**)&xh,    s_xh);
    cudaGetSymbolAddress((void**)&wqkvh, s_wqkvh);
    cudaGetSymbolAddress((void**)&woh,   s_woh);
    cudaGetSymbolAddress((void**)&qh,    s_qh);
    cudaGetSymbolAddress((void**)&kh,    s_kh);
    cudaGetSymbolAddress((void**)&vh,    s_vh);
    cudaGetSymbolAddress((void**)&ath,   s_ath);

    cudaFuncSetAttribute(gemm1, cudaFuncAttributeMaxDynamicSharedMemorySize, 61440);
    cudaFuncSetAttribute(attn_kernel, cudaFuncAttributeMaxDynamicSharedMemorySize, 69632);

    // merged operand prep (all single fp16)
    const int PREP_ITEMS = N4X * 3 + N4KV * 2;
    prep_all<<<PREP_ITEMS / 256, 256>>>(x, wq, wk, wv, wo, xh, wqkvh, woh);

    // fused QKV projection: [2048, 3072] = x @ [wq|wk|wv]^T
    gemm1<<<dim3(24, 16), 256, 61440>>>(xh, wqkvh, qkvf, SLEN, 3072, DMODEL);

    // RMSNorm + RoPE + convert (q pre-scaled; all single fp16)
    norm_rope_cvt<<<(SLEN * 24 * 32) / 256, 256>>>(qkvf, freqs, qh, kh, vh);

    // causal flash attention with sink scaling (heavy-first, K ping-pong)
    attn_kernel<<<dim3(NH, SLEN / 64), 128, 69632>>>(qh, kh, vh, sinks, ath);

    // output projection
    gemm1<<<dim3(16, 16), 256, 61440>>>(ath, woh, out, SLEN, DMODEL, DMODEL);
}

// round 15
// speedup vs baseline: 1.0218x; 1.0218x over previous
#include <cuda_runtime.h>
#include <cuda_fp16.h>
#include <math.h>

typedef unsigned int u32;

#define SLEN 2048
#define DMODEL 2048
#define NH 16
#define NKV 4
#define HD 128
#define MX (SLEN * DMODEL)          // 4194304
#define MKV (SLEN * NKV * HD)       // 1048576
#define WKV (NKV * HD * DMODEL)     // 1048576
#define N4X (MX / 4)                // 1048576 float4 items
#define N4KV (WKV / 4)              // 262144

// fp16 operands
__device__ __align__(16) __half s_xh[MX];                    // x single
__device__ __align__(16) __half s_wqkvh[3072 * DMODEL];      // packed wq|wk|wv, single
__device__ __align__(16) __half s_woh[MX];                   // wo, single
__device__ __align__(16) __half s_qh[MX];                    // q single (post norm+rope, pre-scaled)
__device__ __align__(16) __half s_kh[MKV];                   // k single (post norm+rope)
__device__ __align__(16) __half s_vh[MKV];                   // v single
__device__ __align__(16) __half s_ath[MX];                   // attention out single

// ---------------------------------------------------------------------------
// helpers
// ---------------------------------------------------------------------------
__device__ __forceinline__ u32 sptr(const void* p) {
    return (u32)__cvta_generic_to_shared(p);
}
__device__ __forceinline__ void ldm4(u32 a, u32& r0, u32& r1, u32& r2, u32& r3) {
    asm volatile("ldmatrix.sync.aligned.m8n8.x4.shared.b16 {%0,%1,%2,%3},[%4];"
                 : "=r"(r0), "=r"(r1), "=r"(r2), "=r"(r3) : "r"(a));
}
__device__ __forceinline__ void ldm4t(u32 a, u32& r0, u32& r1, u32& r2, u32& r3) {
    asm volatile("ldmatrix.sync.aligned.m8n8.x4.trans.shared.b16 {%0,%1,%2,%3},[%4];"
                 : "=r"(r0), "=r"(r1), "=r"(r2), "=r"(r3) : "r"(a));
}
__device__ __forceinline__ void mma_h(float* c, u32 a0, u32 a1, u32 a2, u32 a3,
                                      u32 b0, u32 b1) {
    asm volatile(
        "mma.sync.aligned.m16n8k16.row.col.f32.f16.f16.f32 "
        "{%0,%1,%2,%3},{%4,%5,%6,%7},{%8,%9},{%0,%1,%2,%3};"
        : "+f"(c[0]), "+f"(c[1]), "+f"(c[2]), "+f"(c[3])
        : "r"(a0), "r"(a1), "r"(a2), "r"(a3), "r"(b0), "r"(b1));
}
__device__ __forceinline__ u32 pack2h(__half a, __half b) {
    __half2 t = __halves2half2(a, b);
    return *reinterpret_cast<u32*>(&t);
}
__device__ __forceinline__ u32 cvt2h(float x, float y) {
    return pack2h(__float2half_rn(x), __float2half_rn(y));
}
__device__ __forceinline__ float ex2(float x) {
    float y; asm("ex2.approx.f32 %0, %1;" : "=f"(y) : "f"(x)); return y;
}
__device__ __forceinline__ u32 ex2h2(u32 x) {
    u32 y; asm("ex2.approx.f16x2 %0, %1;" : "=r"(y) : "r"(x)); return y;
}
__device__ __forceinline__ void cpa16(u32 dst, const void* src) {
    asm volatile("cp.async.cg.shared.global [%0], [%1], 16;" :: "r"(dst), "l"(src));
}
__device__ __forceinline__ void cpcommit() {
    asm volatile("cp.async.commit_group;");
}
template <int N>
__device__ __forceinline__ void cpwait() {
    asm volatile("cp.async.wait_group %0;" :: "n"(N));
}

// ---------------------------------------------------------------------------
// merged prep: convert x -> xh ; wq|wk|wv -> wqkvh ; wo -> woh (all single)
// ---------------------------------------------------------------------------
__global__ __launch_bounds__(256) void prep_all(
    const float* __restrict__ x, const float* __restrict__ wq,
    const float* __restrict__ wk, const float* __restrict__ wv,
    const float* __restrict__ wo,
    __half* __restrict__ xh, __half* __restrict__ wqkvh, __half* __restrict__ woh)
{
    int i = blockIdx.x * blockDim.x + threadIdx.x;
    if (i < N4X) {
        float4 v = ((const float4*)x)[i];
        ((u32*)xh)[i * 2]     = cvt2h(v.x, v.y);
        ((u32*)xh)[i * 2 + 1] = cvt2h(v.z, v.w);
        return;
    }
    i -= N4X;
    if (i < N4X) {
        float4 v = ((const float4*)wq)[i];
        ((u32*)wqkvh)[i * 2]     = cvt2h(v.x, v.y);
        ((u32*)wqkvh)[i * 2 + 1] = cvt2h(v.z, v.w);
        return;
    }
    i -= N4X;
    if (i < N4KV) {
        float4 v = ((const float4*)wk)[i];
        u32* dst = (u32*)(wqkvh + MX);
        dst[i * 2]     = cvt2h(v.x, v.y);
        dst[i * 2 + 1] = cvt2h(v.z, v.w);
        return;
    }
    i -= N4KV;
    if (i < N4KV) {
        float4 v = ((const float4*)wv)[i];
        u32* dst = (u32*)(wqkvh + MX + WKV);
        dst[i * 2]     = cvt2h(v.x, v.y);
        dst[i * 2 + 1] = cvt2h(v.z, v.w);
        return;
    }
    i -= N4KV;
    {
        float4 v = ((const float4*)wo)[i];
        ((u32*)woh)[i * 2]     = cvt2h(v.x, v.y);
        ((u32*)woh)[i * 2 + 1] = cvt2h(v.z, v.w);
    }
}

// ---------------------------------------------------------------------------
// C[M,N] = A[M,K] @ B[N,K]^T ; both single fp16, 1-term MMA.
// 128x128x32 tiles, 256 thr (8 warps: 4m x 2n), 3-stage cp.async ring.
// FUSE=0: plain fp32 C epilogue (WO projection).
// FUSE=1: QKV epilogue — each n-tile is exactly one head (HD=128):
//   heads 0-15  q: RMSNorm + RoPE + CS prescale -> qh (fp16)
//   heads 16-19 k: RMSNorm + RoPE              -> kh (fp16)
//   heads 20-23 v: plain convert               -> vh (fp16)
// Row sum-of-squares: quad shfl + cross-n-warp exchange via 1KB smem
// (stage smem is dead after the mainloop's final barrier).
// ---------------------------------------------------------------------------
template <int FUSE>
__global__ __launch_bounds__(256, 2) void gemm_t(
    const __half* __restrict__ Ah, const __half* __restrict__ Bh,
    float* __restrict__ C,
    __half* __restrict__ qh, __half* __restrict__ kh, __half* __restrict__ vh,
    const float* __restrict__ freqs, int M, int N, int K)
{
    extern __shared__ char smd[];
    const u32 smb = sptr(smd);
    const int tid = threadIdx.x, lane = tid & 31, w = tid >> 5;
    const int wm = w >> 1, wn = w & 1;
    const int bm = blockIdx.y * 128, bn = blockIdx.x * 128;

    float acc[2][8][4];
#pragma unroll
    for (int a = 0; a < 2; a++)
#pragma unroll
        for (int b = 0; b < 8; b++)
#pragma unroll
            for (int c = 0; c < 4; c++) acc[a][b][c] = 0.f;

    const u32 aoff = (wm * 32 + (lane & 15)) * 80 + (lane >> 4) * 16;
    const u32 boff = 10240 + (wn * 64 + (lane >> 4) * 8 + (lane & 7)) * 80
                     + ((lane >> 3) & 1) * 16;

    auto load_stage = [&](int stg, int k0) {
        u32 sb = smb + stg * 20480;
#pragma unroll
        for (int p = 0; p < 2; p++) {
            int c = tid + p * 256;
            int row = c >> 2, kc = (c & 3) * 8;
            u32 d = sb + row * 80 + kc * 2;
            size_t ga = (size_t)(bm + row) * K + k0 + kc;
            size_t gb = (size_t)(bn + row) * K + k0 + kc;
            cpa16(d,         Ah + ga);
            cpa16(d + 10240, Bh + gb);
        }
        cpcommit();
    };

    const int NCH = K >> 5;
    load_stage(0, 0);
    load_stage(1, 32);

    int stg = 0;
    for (int ic = 0; ic < NCH; ic++) {
        if (ic + 2 < NCH) {
            int nxt = stg + 2; if (nxt >= 3) nxt -= 3;
            load_stage(nxt, (ic + 2) * 32);
            cpwait<2>();
        } else if (ic + 1 < NCH) {
            cpwait<1>();
        } else {
            cpwait<0>();
        }
        __syncthreads();
        const u32 base = smb + stg * 20480;
        const u32 a_ = base + aoff;
        const u32 b_ = base + boff;
#pragma unroll
        for (int ks = 0; ks < 2; ks++) {
            u32 ah[2][4];
            ldm4(a_ + ks * 32,        ah[0][0], ah[0][1], ah[0][2], ah[0][3]);
            ldm4(a_ + ks * 32 + 1280, ah[1][0], ah[1][1], ah[1][2], ah[1][3]);
#pragma unroll
            for (int g = 0; g < 4; g++) {
                u32 bh[4];
                ldm4(b_ + g * 1280 + ks * 32, bh[0], bh[1], bh[2], bh[3]);
#pragma unroll
                for (int mt = 0; mt < 2; mt++)
#pragma unroll
                    for (int s = 0; s < 2; s++)
                        mma_h(acc[mt][g * 2 + s],
                              ah[mt][0], ah[mt][1], ah[mt][2], ah[mt][3],
                              bh[2 * s], bh[2 * s + 1]);
            }
        }
        __syncthreads();
        stg = (stg + 1 == 3) ? 0 : stg + 1;
    }

    if (FUSE == 0) {
#pragma unroll
        for (int mt = 0; mt < 2; mt++)
#pragma unroll
            for (int nt = 0; nt < 8; nt++) {
                int row = bm + wm * 32 + mt * 16 + (lane >> 2);
                int col = bn + wn * 64 + nt * 8 + (lane & 3) * 2;
                *(float2*)&C[(size_t)row * N + col] =
                    make_float2(acc[mt][nt][0], acc[mt][nt][1]);
                *(float2*)&C[(size_t)(row + 8) * N + col] =
                    make_float2(acc[mt][nt][2], acc[mt][nt][3]);
            }
        return;
    }

    // ---- FUSE=1: fused RMSNorm + RoPE + fp16 convert ----
    const float CS = 0.08838834764831845f * 1.4426950408889634f; // scale*log2e
    const int head = blockIdx.x;              // n-tile == head (HD == 128)
    float* rowsum = (float*)smd;              // [2][128] (stage smem is dead)

    if (head < 20) {
#pragma unroll
        for (int mt = 0; mt < 2; mt++)
#pragma unroll
            for (int i = 0; i < 2; i++) {
                float ssum = 0.f;
#pragma unroll
                for (int nt = 0; nt < 8; nt++) {
                    float a0 = acc[mt][nt][2 * i], a1 = acc[mt][nt][2 * i + 1];
                    ssum += a0 * a0 + a1 * a1;
                }
                ssum += __shfl_xor_sync(0xffffffffu, ssum, 1);
                ssum += __shfl_xor_sync(0xffffffffu, ssum, 2);
                if ((lane & 3) == 0) {
                    int rowl = wm * 32 + mt * 16 + (lane >> 2) + i * 8;
                    rowsum[wn * 128 + rowl] = ssum;
                }
            }
    }
    __syncthreads();

#pragma unroll
    for (int mt = 0; mt < 2; mt++)
#pragma unroll
        for (int i = 0; i < 2; i++) {
            int rowl = wm * 32 + mt * 16 + (lane >> 2) + i * 8;
            int s = bm + rowl;
            if (head >= 20) {                 // v: plain convert
                size_t basev = ((size_t)s * NKV + (head - 20)) * HD;
#pragma unroll
                for (int nt = 0; nt < 8; nt++) {
                    int col = wn * 64 + nt * 8 + (lane & 3) * 2;
                    ((u32*)vh)[(basev + col) >> 1] =
                        cvt2h(acc[mt][nt][2 * i], acc[mt][nt][2 * i + 1]);
                }
            } else {                          // q/k: norm + rope
                float tot = rowsum[rowl] + rowsum[128 + rowl];
                float r = rsqrtf(tot * (1.f / 128.f) + 1.1920929e-07f);
                bool isq = (head < 16);
                if (isq) r *= CS;
                size_t baseo = isq ? ((size_t)s * NH + head) * HD
                                   : ((size_t)s * NKV + (head - 16)) * HD;
                u32* dst = (u32*)(isq ? qh : kh);
#pragma unroll
                for (int nt = 0; nt < 8; nt++) {
                    int col = wn * 64 + nt * 8 + (lane & 3) * 2;
                    float2 fc = *(const float2*)&freqs[(size_t)s * 128 + col];
                    float a0 = acc[mt][nt][2 * i] * r;
                    float a1 = acc[mt][nt][2 * i + 1] * r;
                    dst[(baseo + col) >> 1] =
                        cvt2h(a0 * fc.x - a1 * fc.y, a0 * fc.y + a1 * fc.x);
                }
            }
        }
}

// ---------------------------------------------------------------------------
// Flash attention (causal, sink), FA2 warp layout: 4 warps (128 thr), each
// warp owns 16 q-rows x full 64-wide KV tile. q/k/v/P single fp16.
// K ping-pong buffers; P via ex2.approx.f16x2; 2 syncs/iter.
// Grid (NH, NQT) heavy-first.
// smem: Q 0 (17408), K0 17408, K1 34816, V 52224 -> 69632 B (3 CTA/SM).
// ---------------------------------------------------------------------------
__global__ __launch_bounds__(128, 3) void attn_kernel(
    const __half* __restrict__ qh, const __half* __restrict__ kh,
    const __half* __restrict__ vh, const float* __restrict__ sinks,
    __half* __restrict__ ath)
{
    extern __shared__ char smr[];
    const u32 smb = sptr(smr);

    const int tid = threadIdx.x, lane = tid & 31, w = tid >> 5;
    const int h = blockIdx.x, kvh = h >> 2;
    const int qt = gridDim.y - 1 - blockIdx.y;   // heavy tiles launch first

    // async-load Q tile (single): 64 rows x 256B
#pragma unroll
    for (int i = 0; i < 8; i++) {
        int c = tid + i * 128;
        int r = c >> 4, ck = c & 15;
        u32 d = smb + r * 272 + ck * 16;
        size_t g = ((size_t)(qt * 64 + r) * NH + h) * HD + ck * 8;
        cpa16(d, qh + g);
    }
    auto load_k = [&](int kt, int buf) {
        u32 kbase = smb + 17408 + buf * 17408;
#pragma unroll
        for (int i = 0; i < 4; i++) {
            int c = tid + i * 128;
            int r = c >> 3, ck = c & 7;
            u32 d = kbase + r * 272 + ck * 32;
            size_t g = ((size_t)(kt * 64 + r) * NKV + kvh) * HD + ck * 16;
            cpa16(d,      kh + g);
            cpa16(d + 16, kh + g + 8);
        }
        cpcommit();
    };
    auto load_v = [&](int kt) {
#pragma unroll
        for (int i = 0; i < 4; i++) {
            int c = tid + i * 128;
            int r = c >> 3, ck = c & 7;
            u32 d = smb + 52224 + r * 272 + ck * 32;
            size_t g = ((size_t)(kt * 64 + r) * NKV + kvh) * HD + ck * 16;
            cpa16(d,      vh + g);
            cpa16(d + 16, vh + g + 8);
        }
        cpcommit();
    };
    load_k(0, 0);   // Q + K(0) in one group

    float oacc[16][4];
#pragma unroll
    for (int a = 0; a < 16; a++)
#pragma unroll
        for (int c = 0; c < 4; c++) oacc[a][c] = 0.f;
    float mrow[2] = {-1e30f, -1e30f}, lrow[2] = {0.f, 0.f};

    const u32 qa = smb + (w * 16 + (lane & 15)) * 272 + (lane >> 4) * 16;
    const u32 kboff = ((lane >> 4) * 8 + (lane & 7)) * 272 + ((lane >> 3) & 1) * 16;
    const u32 vb = smb + 52224 + (((lane >> 3) & 1) * 8 + (lane & 7)) * 272
                   + ((lane >> 4) * 8) * 2;

    for (int kt = 0; kt <= qt; kt++) {
        cpwait<0>();       // K(kt) (+Q first iter) arrived
        __syncthreads();   // (B) K visible; prev PV done with V

        load_v(kt);                                 // flies during QK+softmax
        if (kt < qt) load_k(kt + 1, (kt + 1) & 1);  // other buffer

        const u32 kb = smb + 17408 + (kt & 1) * 17408 + kboff;
        float sacc[8][4];
#pragma unroll
        for (int a = 0; a < 8; a++)
#pragma unroll
            for (int c = 0; c < 4; c++) sacc[a][c] = 0.f;

#pragma unroll
        for (int ks = 0; ks < 8; ks++) {
            u32 ah0, ah1, ah2, ah3;
            ldm4(qa + ks * 32, ah0, ah1, ah2, ah3);
#pragma unroll
            for (int g = 0; g < 4; g++) {
                u32 bh[4];
                ldm4(kb + g * 4352 + ks * 32, bh[0], bh[1], bh[2], bh[3]);
#pragma unroll
                for (int s = 0; s < 2; s++)
                    mma_h(sacc[g * 2 + s], ah0, ah1, ah2, ah3,
                          bh[2 * s], bh[2 * s + 1]);
            }
        }
        // no sync: K(kt+1) targets the other buffer

        if (kt == qt) {
            int r0 = qt * 64 + w * 16 + (lane >> 2);
#pragma unroll
            for (int nt = 0; nt < 8; nt++) {
                int col0 = kt * 64 + nt * 8 + (lane & 3) * 2;
#pragma unroll
                for (int ci = 0; ci < 4; ci++) {
                    int row = r0 + ((ci >= 2) ? 8 : 0);
                    int col = col0 + (ci & 1);
                    if (col > row) sacc[nt][ci] = -1e30f;
                }
            }
        }

        u32 preg[2][8];
        float alpha[2];
#pragma unroll
        for (int i = 0; i < 2; i++) {
            float rm = -1e30f;
#pragma unroll
            for (int nt = 0; nt < 8; nt++)
                rm = fmaxf(rm, fmaxf(sacc[nt][2 * i], sacc[nt][2 * i + 1]));
            rm = fmaxf(rm, __shfl_xor_sync(0xffffffffu, rm, 1));
            rm = fmaxf(rm, __shfl_xor_sync(0xffffffffu, rm, 2));
            float mn = fmaxf(mrow[i], rm);
            alpha[i] = ex2(mrow[i] - mn);
            mrow[i] = mn;
            float rs = 0.f;
#pragma unroll
            for (int nt = 0; nt < 8; nt++) {
                u32 xp = cvt2h(sacc[nt][2 * i] - mn, sacc[nt][2 * i + 1] - mn);
                u32 pp = ex2h2(xp);
                preg[i][nt] = pp;
                float2 pf = __half22float2(*reinterpret_cast<__half2*>(&pp));
                rs += pf.x + pf.y;
            }
            rs += __shfl_xor_sync(0xffffffffu, rs, 1);
            rs += __shfl_xor_sync(0xffffffffu, rs, 2);
            lrow[i] = lrow[i] * alpha[i] + rs;
#pragma unroll
            for (int nt = 0; nt < 16; nt++) {
                oacc[nt][2 * i]     *= alpha[i];
                oacc[nt][2 * i + 1] *= alpha[i];
            }
        }

        cpwait<1>();       // V(kt) done (K(kt+1) may still fly)
        if (kt == qt) cpwait<0>();
        __syncthreads();   // (D) V visible

#pragma unroll
        for (int j = 0; j < 4; j++) {
            u32 ph0 = preg[0][2 * j],     ph1 = preg[1][2 * j];
            u32 ph2 = preg[0][2 * j + 1], ph3 = preg[1][2 * j + 1];
#pragma unroll
            for (int g = 0; g < 8; g++) {
                u32 bh[4];
                ldm4t(vb + j * 4352 + g * 32, bh[0], bh[1], bh[2], bh[3]);
#pragma unroll
                for (int s = 0; s < 2; s++)
                    mma_h(oacc[g * 2 + s], ph0, ph1, ph2, ph3,
                          bh[2 * s], bh[2 * s + 1]);
            }
        }
    }

    // epilogue: lse, sink sigmoid, normalize, single-fp16 store
    float sk = sinks[h];
#pragma unroll
    for (int i = 0; i < 2; i++) {
        float lse = mrow[i] * 0.6931471805599453f + logf(lrow[i]);
        float sg = 1.f / (1.f + expf(sk - lse));
        float sc = sg / lrow[i];
        int row = qt * 64 + w * 16 + (lane >> 2) + i * 8;
        size_t rb = (size_t)row * DMODEL + h * HD;
#pragma unroll
        for (int nt = 0; nt < 16; nt++) {
            int col = nt * 8 + (lane & 3) * 2;
            ((u32*)ath)[(rb + col) >> 1] =
                cvt2h(oacc[nt][2 * i] * sc, oacc[nt][2 * i + 1] * sc);
        }
    }
}

// ---------------------------------------------------------------------------
extern "C" void kernel_launch(void* const* d_in, const int* in_sizes, int n_in,
                              void* d_out, int out_size)
{
    const float* x     = (const float*)d_in[0];
    const float* freqs = (const float*)d_in[1];
    const float* wq    = (const float*)d_in[2];
    const float* wk    = (const float*)d_in[3];
    const float* wv    = (const float*)d_in[4];
    const float* wo    = (const float*)d_in[5];
    const float* sinks = (const float*)d_in[6];
    float* out = (float*)d_out;

    __half *xh, *wqkvh, *woh, *qh, *kh, *vh, *ath;
    cudaGetSymbolAddress((void**)&xh,    s_xh);
    cudaGetSymbolAddress((void**)&wqkvh, s_wqkvh);
    cudaGetSymbolAddress((void**)&woh,   s_woh);
    cudaGetSymbolAddress((void**)&qh,    s_qh);
    cudaGetSymbolAddress((void**)&kh,    s_kh);
    cudaGetSymbolAddress((void**)&vh,    s_vh);
    cudaGetSymbolAddress((void**)&ath,   s_ath);

    cudaFuncSetAttribute(gemm_t<0>, cudaFuncAttributeMaxDynamicSharedMemorySize, 61440);
    cudaFuncSetAttribute(gemm_t<1>, cudaFuncAttributeMaxDynamicSharedMemorySize, 61440);
    cudaFuncSetAttribute(attn_kernel, cudaFuncAttributeMaxDynamicSharedMemorySize, 69632);

    // merged operand prep (all single fp16)
    const int PREP_ITEMS = N4X * 3 + N4KV * 2;
    prep_all<<<PREP_ITEMS / 256, 256>>>(x, wq, wk, wv, wo, xh, wqkvh, woh);

    // fused QKV projection + RMSNorm + RoPE + fp16 convert (per-head n-tiles)
    gemm_t<1><<<dim3(24, 16), 256, 61440>>>(xh, wqkvh, nullptr, qh, kh, vh,
                                            freqs, SLEN, 3072, DMODEL);

    // causal flash attention with sink scaling (heavy-first, K ping-pong)
    attn_kernel<<<dim3(NH, SLEN / 64), 128, 69632>>>(qh, kh, vh, sinks, ath);

    // output projection
    gemm_t<0><<<dim3(16, 16), 256, 61440>>>(ath, woh, out, nullptr, nullptr,
                                            nullptr, nullptr, SLEN, DMODEL, DMODEL);
}

// round 16
// speedup vs baseline: 1.0379x; 1.0158x over previous
#include <cuda_runtime.h>
#include <cuda_fp16.h>
#include <math.h>

typedef unsigned int u32;

#define SLEN 2048
#define DMODEL 2048
#define NH 16
#define NKV 4
#define HD 128
#define MX (SLEN * DMODEL)          // 4194304
#define MKV (SLEN * NKV * HD)       // 1048576
#define WKV (NKV * HD * DMODEL)     // 1048576
#define N4X (MX / 4)                // 1048576 float4 items
#define N4KV (WKV / 4)              // 262144

// fp16 operands
__device__ __align__(16) __half s_xh[MX];                    // x single
__device__ __align__(16) __half s_wqkvh[3072 * DMODEL];      // packed wq|wk|wv, single
__device__ __align__(16) __half s_woh[MX];                   // wo, single
__device__ __align__(16) __half s_qh[MX];                    // q single (post norm+rope, pre-scaled)
__device__ __align__(16) __half s_kh[MKV];                   // k single (post norm+rope)
__device__ __align__(16) __half s_vh[MKV];                   // v single
__device__ __align__(16) __half s_ath[MX];                   // attention out single

// ---------------------------------------------------------------------------
// helpers
// ---------------------------------------------------------------------------
__device__ __forceinline__ u32 sptr(const void* p) {
    return (u32)__cvta_generic_to_shared(p);
}
__device__ __forceinline__ void ldm4(u32 a, u32& r0, u32& r1, u32& r2, u32& r3) {
    asm volatile("ldmatrix.sync.aligned.m8n8.x4.shared.b16 {%0,%1,%2,%3},[%4];"
                 : "=r"(r0), "=r"(r1), "=r"(r2), "=r"(r3) : "r"(a));
}
__device__ __forceinline__ void ldm4t(u32 a, u32& r0, u32& r1, u32& r2, u32& r3) {
    asm volatile("ldmatrix.sync.aligned.m8n8.x4.trans.shared.b16 {%0,%1,%2,%3},[%4];"
                 : "=r"(r0), "=r"(r1), "=r"(r2), "=r"(r3) : "r"(a));
}
__device__ __forceinline__ void mma_h(float* c, u32 a0, u32 a1, u32 a2, u32 a3,
                                      u32 b0, u32 b1) {
    asm volatile(
        "mma.sync.aligned.m16n8k16.row.col.f32.f16.f16.f32 "
        "{%0,%1,%2,%3},{%4,%5,%6,%7},{%8,%9},{%0,%1,%2,%3};"
        : "+f"(c[0]), "+f"(c[1]), "+f"(c[2]), "+f"(c[3])
        : "r"(a0), "r"(a1), "r"(a2), "r"(a3), "r"(b0), "r"(b1));
}
__device__ __forceinline__ u32 pack2h(__half a, __half b) {
    __half2 t = __halves2half2(a, b);
    return *reinterpret_cast<u32*>(&t);
}
__device__ __forceinline__ u32 cvt2h(float x, float y) {
    return pack2h(__float2half_rn(x), __float2half_rn(y));
}
__device__ __forceinline__ float ex2(float x) {
    float y; asm("ex2.approx.f32 %0, %1;" : "=f"(y) : "f"(x)); return y;
}
__device__ __forceinline__ u32 ex2h2(u32 x) {
    u32 y; asm("ex2.approx.f16x2 %0, %1;" : "=r"(y) : "r"(x)); return y;
}
__device__ __forceinline__ void cpa16(u32 dst, const void* src) {
    asm volatile("cp.async.cg.shared.global [%0], [%1], 16;" :: "r"(dst), "l"(src));
}
__device__ __forceinline__ void cpcommit() {
    asm volatile("cp.async.commit_group;");
}
template <int N>
__device__ __forceinline__ void cpwait() {
    asm volatile("cp.async.wait_group %0;" :: "n"(N));
}

// ---------------------------------------------------------------------------
// merged prep: convert x -> xh ; wq|wk|wv -> wqkvh ; wo -> woh (all single)
// ---------------------------------------------------------------------------
__global__ __launch_bounds__(256) void prep_all(
    const float* __restrict__ x, const float* __restrict__ wq,
    const float* __restrict__ wk, const float* __restrict__ wv,
    const float* __restrict__ wo,
    __half* __restrict__ xh, __half* __restrict__ wqkvh, __half* __restrict__ woh)
{
    int i = blockIdx.x * blockDim.x + threadIdx.x;
    if (i < N4X) {
        float4 v = ((const float4*)x)[i];
        ((u32*)xh)[i * 2]     = cvt2h(v.x, v.y);
        ((u32*)xh)[i * 2 + 1] = cvt2h(v.z, v.w);
        return;
    }
    i -= N4X;
    if (i < N4X) {
        float4 v = ((const float4*)wq)[i];
        ((u32*)wqkvh)[i * 2]     = cvt2h(v.x, v.y);
        ((u32*)wqkvh)[i * 2 + 1] = cvt2h(v.z, v.w);
        return;
    }
    i -= N4X;
    if (i < N4KV) {
        float4 v = ((const float4*)wk)[i];
        u32* dst = (u32*)(wqkvh + MX);
        dst[i * 2]     = cvt2h(v.x, v.y);
        dst[i * 2 + 1] = cvt2h(v.z, v.w);
        return;
    }
    i -= N4KV;
    if (i < N4KV) {
        float4 v = ((const float4*)wv)[i];
        u32* dst = (u32*)(wqkvh + MX + WKV);
        dst[i * 2]     = cvt2h(v.x, v.y);
        dst[i * 2 + 1] = cvt2h(v.z, v.w);
        return;
    }
    i -= N4KV;
    {
        float4 v = ((const float4*)wo)[i];
        ((u32*)woh)[i * 2]     = cvt2h(v.x, v.y);
        ((u32*)woh)[i * 2 + 1] = cvt2h(v.z, v.w);
    }
}

// ---------------------------------------------------------------------------
// C[M,N] = A[M,K] @ B[N,K]^T ; both single fp16, 1-term MMA.
// 128x128x32 tiles, 256 thr (8 warps: 4m x 2n), 3-stage cp.async ring,
// SINGLE sync per chunk: cpwait -> sync -> load(ic+2) -> compute.
// (top-of-iter sync both publishes chunk ic and frees stage (ic-1)%3,
//  which is exactly the stage load(ic+2) targets.)
// FUSE=1: QKV epilogue with fused RMSNorm+RoPE+fp16 convert (n-tile==head).
// ---------------------------------------------------------------------------
template <int FUSE>
__global__ __launch_bounds__(256, 2) void gemm_t(
    const __half* __restrict__ Ah, const __half* __restrict__ Bh,
    float* __restrict__ C,
    __half* __restrict__ qh, __half* __restrict__ kh, __half* __restrict__ vh,
    const float* __restrict__ freqs, int M, int N, int K)
{
    extern __shared__ char smd[];
    const u32 smb = sptr(smd);
    const int tid = threadIdx.x, lane = tid & 31, w = tid >> 5;
    const int wm = w >> 1, wn = w & 1;
    const int bm = blockIdx.y * 128, bn = blockIdx.x * 128;

    float acc[2][8][4];
#pragma unroll
    for (int a = 0; a < 2; a++)
#pragma unroll
        for (int b = 0; b < 8; b++)
#pragma unroll
            for (int c = 0; c < 4; c++) acc[a][b][c] = 0.f;

    const u32 aoff = (wm * 32 + (lane & 15)) * 80 + (lane >> 4) * 16;
    const u32 boff = 10240 + (wn * 64 + (lane >> 4) * 8 + (lane & 7)) * 80
                     + ((lane >> 3) & 1) * 16;

    auto load_stage = [&](int stg, int k0) {
        u32 sb = smb + stg * 20480;
#pragma unroll
        for (int p = 0; p < 2; p++) {
            int c = tid + p * 256;
            int row = c >> 2, kc = (c & 3) * 8;
            u32 d = sb + row * 80 + kc * 2;
            size_t ga = (size_t)(bm + row) * K + k0 + kc;
            size_t gb = (size_t)(bn + row) * K + k0 + kc;
            cpa16(d,         Ah + ga);
            cpa16(d + 10240, Bh + gb);
        }
        cpcommit();
    };

    const int NCH = K >> 5;
    load_stage(0, 0);
    load_stage(1, 32);

    int stg = 0;
    for (int ic = 0; ic < NCH; ic++) {
        if (ic + 1 < NCH) cpwait<1>(); else cpwait<0>();
        __syncthreads();                 // publish chunk ic; free stage (ic-1)%3
        if (ic + 2 < NCH) {
            int nxt = stg + 2; if (nxt >= 3) nxt -= 3;
            load_stage(nxt, (ic + 2) * 32);
        }
        const u32 base = smb + stg * 20480;
        const u32 a_ = base + aoff;
        const u32 b_ = base + boff;
#pragma unroll
        for (int ks = 0; ks < 2; ks++) {
            u32 ah[2][4];
            ldm4(a_ + ks * 32,        ah[0][0], ah[0][1], ah[0][2], ah[0][3]);
            ldm4(a_ + ks * 32 + 1280, ah[1][0], ah[1][1], ah[1][2], ah[1][3]);
#pragma unroll
            for (int g = 0; g < 4; g++) {
                u32 bh[4];
                ldm4(b_ + g * 1280 + ks * 32, bh[0], bh[1], bh[2], bh[3]);
#pragma unroll
                for (int mt = 0; mt < 2; mt++)
#pragma unroll
                    for (int s = 0; s < 2; s++)
                        mma_h(acc[mt][g * 2 + s],
                              ah[mt][0], ah[mt][1], ah[mt][2], ah[mt][3],
                              bh[2 * s], bh[2 * s + 1]);
            }
        }
        stg = (stg + 1 == 3) ? 0 : stg + 1;
    }

    if (FUSE == 0) {
#pragma unroll
        for (int mt = 0; mt < 2; mt++)
#pragma unroll
            for (int nt = 0; nt < 8; nt++) {
                int row = bm + wm * 32 + mt * 16 + (lane >> 2);
                int col = bn + wn * 64 + nt * 8 + (lane & 3) * 2;
                *(float2*)&C[(size_t)row * N + col] =
                    make_float2(acc[mt][nt][0], acc[mt][nt][1]);
                *(float2*)&C[(size_t)(row + 8) * N + col] =
                    make_float2(acc[mt][nt][2], acc[mt][nt][3]);
            }
        return;
    }

    // ---- FUSE=1: fused RMSNorm + RoPE + fp16 convert ----
    const float CS = 0.08838834764831845f * 1.4426950408889634f; // scale*log2e
    const int head = blockIdx.x;              // n-tile == head (HD == 128)
    float* rowsum = (float*)smd;              // [2][128]

    __syncthreads();                          // last compute done before smem reuse
    if (head < 20) {
#pragma unroll
        for (int mt = 0; mt < 2; mt++)
#pragma unroll
            for (int i = 0; i < 2; i++) {
                float ssum = 0.f;
#pragma unroll
                for (int nt = 0; nt < 8; nt++) {
                    float a0 = acc[mt][nt][2 * i], a1 = acc[mt][nt][2 * i + 1];
                    ssum += a0 * a0 + a1 * a1;
                }
                ssum += __shfl_xor_sync(0xffffffffu, ssum, 1);
                ssum += __shfl_xor_sync(0xffffffffu, ssum, 2);
                if ((lane & 3) == 0) {
                    int rowl = wm * 32 + mt * 16 + (lane >> 2) + i * 8;
                    rowsum[wn * 128 + rowl] = ssum;
                }
            }
    }
    __syncthreads();

#pragma unroll
    for (int mt = 0; mt < 2; mt++)
#pragma unroll
        for (int i = 0; i < 2; i++) {
            int rowl = wm * 32 + mt * 16 + (lane >> 2) + i * 8;
            int s = bm + rowl;
            if (head >= 20) {                 // v: plain convert
                size_t basev = ((size_t)s * NKV + (head - 20)) * HD;
#pragma unroll
                for (int nt = 0; nt < 8; nt++) {
                    int col = wn * 64 + nt * 8 + (lane & 3) * 2;
                    ((u32*)vh)[(basev + col) >> 1] =
                        cvt2h(acc[mt][nt][2 * i], acc[mt][nt][2 * i + 1]);
                }
            } else {                          // q/k: norm + rope
                float tot = rowsum[rowl] + rowsum[128 + rowl];
                float r = rsqrtf(tot * (1.f / 128.f) + 1.1920929e-07f);
                bool isq = (head < 16);
                if (isq) r *= CS;
                size_t baseo = isq ? ((size_t)s * NH + head) * HD
                                   : ((size_t)s * NKV + (head - 16)) * HD;
                u32* dst = (u32*)(isq ? qh : kh);
#pragma unroll
                for (int nt = 0; nt < 8; nt++) {
                    int col = wn * 64 + nt * 8 + (lane & 3) * 2;
                    float2 fc = *(const float2*)&freqs[(size_t)s * 128 + col];
                    float a0 = acc[mt][nt][2 * i] * r;
                    float a1 = acc[mt][nt][2 * i + 1] * r;
                    dst[(baseo + col) >> 1] =
                        cvt2h(a0 * fc.x - a1 * fc.y, a0 * fc.y + a1 * fc.x);
                }
            }
        }
}

// ---------------------------------------------------------------------------
// Flash attention (causal, sink), FA2 warp layout: 4 warps (128 thr), each
// warp owns 16 q-rows x full 64-wide KV tile. q/k/v/P single fp16.
// K ping-pong; V+K(kt+1) issued BEFORE QK; P via ex2.approx.f16x2;
// alpha==1 warp-vote skips the oacc rescale (exact). 2 syncs/iter.
// Grid (NH, NQT) heavy-first.
// smem: Q 0 (17408), K0 17408, K1 34816, V 52224 -> 69632 B (3 CTA/SM).
// ---------------------------------------------------------------------------
__global__ __launch_bounds__(128, 3) void attn_kernel(
    const __half* __restrict__ qh, const __half* __restrict__ kh,
    const __half* __restrict__ vh, const float* __restrict__ sinks,
    __half* __restrict__ ath)
{
    extern __shared__ char smr[];
    const u32 smb = sptr(smr);

    const int tid = threadIdx.x, lane = tid & 31, w = tid >> 5;
    const int h = blockIdx.x, kvh = h >> 2;
    const int qt = gridDim.y - 1 - blockIdx.y;   // heavy tiles launch first

    // async-load Q tile (single): 64 rows x 256B
#pragma unroll
    for (int i = 0; i < 8; i++) {
        int c = tid + i * 128;
        int r = c >> 4, ck = c & 15;
        u32 d = smb + r * 272 + ck * 16;
        size_t g = ((size_t)(qt * 64 + r) * NH + h) * HD + ck * 8;
        cpa16(d, qh + g);
    }
    auto load_k = [&](int kt, int buf) {
        u32 kbase = smb + 17408 + buf * 17408;
#pragma unroll
        for (int i = 0; i < 4; i++) {
            int c = tid + i * 128;
            int r = c >> 3, ck = c & 7;
            u32 d = kbase + r * 272 + ck * 32;
            size_t g = ((size_t)(kt * 64 + r) * NKV + kvh) * HD + ck * 16;
            cpa16(d,      kh + g);
            cpa16(d + 16, kh + g + 8);
        }
        cpcommit();
    };
    auto load_v = [&](int kt) {
#pragma unroll
        for (int i = 0; i < 4; i++) {
            int c = tid + i * 128;
            int r = c >> 3, ck = c & 7;
            u32 d = smb + 52224 + r * 272 + ck * 32;
            size_t g = ((size_t)(kt * 64 + r) * NKV + kvh) * HD + ck * 16;
            cpa16(d,      vh + g);
            cpa16(d + 16, vh + g + 8);
        }
        cpcommit();
    };
    load_k(0, 0);   // Q + K(0) in one group

    float oacc[16][4];
#pragma unroll
    for (int a = 0; a < 16; a++)
#pragma unroll
        for (int c = 0; c < 4; c++) oacc[a][c] = 0.f;
    float mrow[2] = {-1e30f, -1e30f}, lrow[2] = {0.f, 0.f};

    const u32 qa = smb + (w * 16 + (lane & 15)) * 272 + (lane >> 4) * 16;
    const u32 kboff = ((lane >> 4) * 8 + (lane & 7)) * 272 + ((lane >> 3) & 1) * 16;
    const u32 vb = smb + 52224 + (((lane >> 3) & 1) * 8 + (lane & 7)) * 272
                   + ((lane >> 4) * 8) * 2;

    for (int kt = 0; kt <= qt; kt++) {
        cpwait<0>();       // K(kt) (+Q first iter) arrived; V(kt-1) done earlier
        __syncthreads();   // (B) K visible; prev PV done with V buffer

        load_v(kt);                                 // both fly through QK+softmax
        if (kt < qt) load_k(kt + 1, (kt + 1) & 1);  // other K buffer

        const u32 kb = smb + 17408 + (kt & 1) * 17408 + kboff;
        float sacc[8][4];
#pragma unroll
        for (int a = 0; a < 8; a++)
#pragma unroll
            for (int c = 0; c < 4; c++) sacc[a][c] = 0.f;

#pragma unroll
        for (int ks = 0; ks < 8; ks++) {
            u32 ah0, ah1, ah2, ah3;
            ldm4(qa + ks * 32, ah0, ah1, ah2, ah3);
#pragma unroll
            for (int g = 0; g < 4; g++) {
                u32 bh[4];
                ldm4(kb + g * 4352 + ks * 32, bh[0], bh[1], bh[2], bh[3]);
#pragma unroll
                for (int s = 0; s < 2; s++)
                    mma_h(sacc[g * 2 + s], ah0, ah1, ah2, ah3,
                          bh[2 * s], bh[2 * s + 1]);
            }
        }
        // no sync: K(kt+1) targets the other buffer

        if (kt == qt) {
            int r0 = qt * 64 + w * 16 + (lane >> 2);
#pragma unroll
            for (int nt = 0; nt < 8; nt++) {
                int col0 = kt * 64 + nt * 8 + (lane & 3) * 2;
#pragma unroll
                for (int ci = 0; ci < 4; ci++) {
                    int row = r0 + ((ci >= 2) ? 8 : 0);
                    int col = col0 + (ci & 1);
                    if (col > row) sacc[nt][ci] = -1e30f;
                }
            }
        }

        u32 preg[2][8];
        float alpha[2];
#pragma unroll
        for (int i = 0; i < 2; i++) {
            float rm = -1e30f;
#pragma unroll
            for (int nt = 0; nt < 8; nt++)
                rm = fmaxf(rm, fmaxf(sacc[nt][2 * i], sacc[nt][2 * i + 1]));
            rm = fmaxf(rm, __shfl_xor_sync(0xffffffffu, rm, 1));
            rm = fmaxf(rm, __shfl_xor_sync(0xffffffffu, rm, 2));
            float mn = fmaxf(mrow[i], rm);
            alpha[i] = ex2(mrow[i] - mn);
            mrow[i] = mn;
            float rs = 0.f;
#pragma unroll
            for (int nt = 0; nt < 8; nt++) {
                u32 xp = cvt2h(sacc[nt][2 * i] - mn, sacc[nt][2 * i + 1] - mn);
                u32 pp = ex2h2(xp);
                preg[i][nt] = pp;
                float2 pf = __half22float2(*reinterpret_cast<__half2*>(&pp));
                rs += pf.x + pf.y;
            }
            rs += __shfl_xor_sync(0xffffffffu, rs, 1);
            rs += __shfl_xor_sync(0xffffffffu, rs, 2);
            lrow[i] = lrow[i] * alpha[i] + rs;
        }
        // exact skip: alpha==1.0 when the running max didn't change
        if (!__all_sync(0xffffffffu, (alpha[0] == 1.f) & (alpha[1] == 1.f))) {
#pragma unroll
            for (int i = 0; i < 2; i++)
#pragma unroll
                for (int nt = 0; nt < 16; nt++) {
                    oacc[nt][2 * i]     *= alpha[i];
                    oacc[nt][2 * i + 1] *= alpha[i];
                }
        }

        cpwait<1>();       // V(kt) done (K(kt+1) may still fly)
        if (kt == qt) cpwait<0>();
        __syncthreads();   // (D) V visible

#pragma unroll
        for (int j = 0; j < 4; j++) {
            u32 ph0 = preg[0][2 * j],     ph1 = preg[1][2 * j];
            u32 ph2 = preg[0][2 * j + 1], ph3 = preg[1][2 * j + 1];
#pragma unroll
            for (int g = 0; g < 8; g++) {
                u32 bh[4];
                ldm4t(vb + j * 4352 + g * 32, bh[0], bh[1], bh[2], bh[3]);
#pragma unroll
                for (int s = 0; s < 2; s++)
                    mma_h(oacc[g * 2 + s], ph0, ph1, ph2, ph3,
                          bh[2 * s], bh[2 * s + 1]);
            }
        }
    }

    // epilogue: lse, sink sigmoid, normalize, single-fp16 store
    float sk = sinks[h];
#pragma unroll
    for (int i = 0; i < 2; i++) {
        float lse = mrow[i] * 0.6931471805599453f + logf(lrow[i]);
        float sg = 1.f / (1.f + expf(sk - lse));
        float sc = sg / lrow[i];
        int row = qt * 64 + w * 16 + (lane >> 2) + i * 8;
        size_t rb = (size_t)row * DMODEL + h * HD;
#pragma unroll
        for (int nt = 0; nt < 16; nt++) {
            int col = nt * 8 + (lane & 3) * 2;
            ((u32*)ath)[(rb + col) >> 1] =
                cvt2h(oacc[nt][2 * i] * sc, oacc[nt][2 * i + 1] * sc);
        }
    }
}

// ---------------------------------------------------------------------------
extern "C" void kernel_launch(void* const* d_in, const int* in_sizes, int n_in,
                              void* d_out, int out_size)
{
    const float* x     = (const float*)d_in[0];
    const float* freqs = (const float*)d_in[1];
    const float* wq    = (const float*)d_in[2];
    const float* wk    = (const float*)d_in[3];
    const float* wv    = (const float*)d_in[4];
    const float* wo    = (const float*)d_in[5];
    const float* sinks = (const float*)d_in[6];
    float* out = (float*)d_out;

    __half *xh, *wqkvh, *woh, *qh, *kh, *vh, *ath;
    cudaGetSymbolAddress((void**)&xh,    s_xh);
    cudaGetSymbolAddress((void**)&wqkvh, s_wqkvh);
    cudaGetSymbolAddress((void**)&woh,   s_woh);
    cudaGetSymbolAddress((void**)&qh,    s_qh);
    cudaGetSymbolAddress((void**)&kh,    s_kh);
    cudaGetSymbolAddress((void**)&vh,    s_vh);
    cudaGetSymbolAddress((void**)&ath,   s_ath);

    cudaFuncSetAttribute(gemm_t<0>, cudaFuncAttributeMaxDynamicSharedMemorySize, 61440);
    cudaFuncSetAttribute(gemm_t<1>, cudaFuncAttributeMaxDynamicSharedMemorySize, 61440);
    cudaFuncSetAttribute(attn_kernel, cudaFuncAttributeMaxDynamicSharedMemorySize, 69632);

    // merged operand prep (all single fp16)
    const int PREP_ITEMS = N4X * 3 + N4KV * 2;
    prep_all<<<PREP_ITEMS / 256, 256>>>(x, wq, wk, wv, wo, xh, wqkvh, woh);

    // fused QKV projection + RMSNorm + RoPE + fp16 convert (per-head n-tiles)
    gemm_t<1><<<dim3(24, 16), 256, 61440>>>(xh, wqkvh, nullptr, qh, kh, vh,
                                            freqs, SLEN, 3072, DMODEL);

    // causal flash attention with sink scaling (heavy-first, K ping-pong)
    attn_kernel<<<dim3(NH, SLEN / 64), 128, 69632>>>(qh, kh, vh, sinks, ath);

    // output projection
    gemm_t<0><<<dim3(16, 16), 256, 61440>>>(ath, woh, out, nullptr, nullptr,
                                            nullptr, nullptr, SLEN, DMODEL, DMODEL);
}